// round 2
// baseline (speedup 1.0000x reference)
#include <cuda_runtime.h>
#include <cuda_bf16.h>
#include <cstdint>

// ---------------------------------------------------------------------------
// Mamba block forward.  B=2, L=2048, d_model=512, d_inner=1024, d_state=16,
// dt_rank=32, d_conv=4.
// Inputs (metadata order):
//  0 x          [2,2048,512]
//  1 in_proj_w  [2048,512]
//  2 conv_w     [1024,1,4]
//  3 conv_b     [1024]
//  4 x_proj_w   [64,1024]
//  5 dt_proj_w  [1024,32]
//  6 dt_proj_b  [1024]
//  7 A_log      [1024,16]
//  8 D_param    [1024]
//  9 out_proj_w [512,1024]
// Output: [2,2048,512] float32
// ---------------------------------------------------------------------------

#define BATCH    2
#define SEQLEN   2048
#define DMODEL   512
#define DINNER   1024
#define DSTATE   16
#define DTRANK   32
#define DCONV    4
#define MROWS    (BATCH * SEQLEN)        // 4096

// Scratch (device-global; no runtime allocation allowed)
__device__ float g_xz[(size_t)MROWS * 2 * DINNER];    // [4096, 2048]  xs | z
__device__ float g_xs[(size_t)MROWS * DINNER];        // conv+silu output
__device__ float g_xdbl[(size_t)MROWS * 64];          // [4096, 64]
__device__ float g_delta[(size_t)MROWS * DINNER];     // softplus(dt@W + b)
__device__ float g_y[(size_t)MROWS * DINNER];         // scan output (gated)

// ---------------------------------------------------------------------------
// Tiled fp32 NT GEMM: C[m,n] = sum_k A[m*lda+k] * W[n*ldw+k]
// BM=BN=64, BK=16, 256 threads, 4x4 microtile.
// STAGE selects operand bindings at compile time (no host-side symbol lookup):
//   1: A=param x      W=in_proj_w  C=g_xz    K=512   ldc=2048
//   3: A=g_xs         W=x_proj_w   C=g_xdbl  K=1024  ldc=64
//   4: A=g_xdbl(:,32) W=dt_proj_w  C=g_delta K=32    ldc=1024  softplus+bias
//   6: A=g_y          W=out_proj_w C=param   K=1024  ldc=512
// ---------------------------------------------------------------------------
template <int STAGE>
__global__ void __launch_bounds__(256)
gemm_nt(const float* __restrict__ Ap,
        const float* __restrict__ W,
        float* __restrict__ Cp,
        const float* __restrict__ bias)
{
    constexpr int BM = 64, BN = 64, BK = 16;

    const float* A;
    float* C;
    int lda, ldw, ldc, K;
    if constexpr (STAGE == 1) {
        A = Ap;     C = g_xz;    lda = DMODEL; ldw = DMODEL; ldc = 2 * DINNER; K = DMODEL;
    } else if constexpr (STAGE == 3) {
        A = g_xs;   C = g_xdbl;  lda = DINNER; ldw = DINNER; ldc = 64;         K = DINNER;
    } else if constexpr (STAGE == 4) {
        A = g_xdbl; C = g_delta; lda = 64;     ldw = DTRANK; ldc = DINNER;     K = DTRANK;
    } else {  // STAGE == 6
        A = g_y;    C = Cp;      lda = DINNER; ldw = DINNER; ldc = DMODEL;     K = DINNER;
    }

    __shared__ float As[BK][BM];
    __shared__ float Bs[BK][BN];

    const int tid = threadIdx.x;
    const int m0 = blockIdx.y * BM;
    const int n0 = blockIdx.x * BN;
    const int tx = tid & 15;          // 0..15
    const int ty = tid >> 4;          // 0..15
    const int lrow = tid >> 2;        // 0..63
    const int lc4 = (tid & 3) * 4;    // 0,4,8,12

    float acc[4][4];
#pragma unroll
    for (int i = 0; i < 4; i++)
#pragma unroll
        for (int j = 0; j < 4; j++) acc[i][j] = 0.f;

    const float* Arow = A + (size_t)(m0 + lrow) * lda + lc4;
    const float* Wrow = W + (size_t)(n0 + lrow) * ldw + lc4;

#pragma unroll 1
    for (int k0 = 0; k0 < K; k0 += BK) {
        float4 av = *(const float4*)(Arow + k0);
        float4 wv = *(const float4*)(Wrow + k0);
        __syncthreads();
        As[lc4 + 0][lrow] = av.x; As[lc4 + 1][lrow] = av.y;
        As[lc4 + 2][lrow] = av.z; As[lc4 + 3][lrow] = av.w;
        Bs[lc4 + 0][lrow] = wv.x; Bs[lc4 + 1][lrow] = wv.y;
        Bs[lc4 + 2][lrow] = wv.z; Bs[lc4 + 3][lrow] = wv.w;
        __syncthreads();
#pragma unroll
        for (int kk = 0; kk < BK; kk++) {
            float4 a4 = *(const float4*)&As[kk][ty * 4];
            float4 b4 = *(const float4*)&Bs[kk][tx * 4];
            float ar[4] = {a4.x, a4.y, a4.z, a4.w};
            float br[4] = {b4.x, b4.y, b4.z, b4.w};
#pragma unroll
            for (int i = 0; i < 4; i++)
#pragma unroll
                for (int j = 0; j < 4; j++)
                    acc[i][j] = fmaf(ar[i], br[j], acc[i][j]);
        }
    }

#pragma unroll
    for (int i = 0; i < 4; i++) {
        const int m = m0 + ty * 4 + i;
#pragma unroll
        for (int j = 0; j < 4; j++) {
            const int n = n0 + tx * 4 + j;
            float v = acc[i][j];
            if constexpr (STAGE == 4) {
                v += bias[n];
                v = (v > 20.f) ? v : log1pf(__expf(v));   // softplus
            }
            C[(size_t)m * ldc + n] = v;
        }
    }
}

// ---------------------------------------------------------------------------
// Causal depthwise conv1d (width 4) + SiLU on the xs half of g_xz.
// One block per (b,l) row.
// ---------------------------------------------------------------------------
__global__ void __launch_bounds__(256)
conv_silu_kernel(const float* __restrict__ conv_w,
                 const float* __restrict__ conv_b)
{
    const int bl = blockIdx.x;            // 0..4095  (= b*L + l)
    const int l = bl & (SEQLEN - 1);
    for (int d = threadIdx.x; d < DINNER; d += blockDim.x) {
        float acc = conv_b[d];
#pragma unroll
        for (int j = 0; j < DCONV; j++) {
            const int ls = l - (DCONV - 1) + j;
            if (ls >= 0)
                acc = fmaf(g_xz[(size_t)(bl - (DCONV - 1) + j) * (2 * DINNER) + d],
                           conv_w[d * DCONV + j], acc);
        }
        const float s = acc / (1.f + __expf(-acc));   // SiLU
        g_xs[(size_t)bl * DINNER + d] = s;
    }
}

// ---------------------------------------------------------------------------
// Selective scan.  One 16-lane group per (b,d) channel; lane n owns state n.
// h <- exp(delta*A[d,n]) * h + delta*u*B[l,n];  y = sum_n h*C[l,n]
// then y = (y + u*D[d]) * silu(z).
// 128 threads/block = 8 channels/block;  grid = 2048/8 = 256 blocks.
// ---------------------------------------------------------------------------
__global__ void __launch_bounds__(128)
scan_kernel(const float* __restrict__ A_log,
            const float* __restrict__ D_param)
{
    const int tid = threadIdx.x;
    const int half = tid >> 4;            // 0..7  channel within block
    const int n = tid & 15;               // state index
    const int hw = blockIdx.x * 8 + half; // global channel id
    const int b = hw >> 10;               // / 1024
    const int d = hw & (DINNER - 1);

    const float A_dn = -__expf(A_log[d * DSTATE + n]);
    const float Dd = D_param[d];

    const float* xd = g_xdbl + (size_t)b * SEQLEN * 64;
    const float* dl = g_delta + (size_t)b * SEQLEN * DINNER + d;
    const float* us = g_xs + (size_t)b * SEQLEN * DINNER + d;
    const float* zp = g_xz + (size_t)b * SEQLEN * (2 * DINNER) + DINNER + d;
    float* yp = g_y + (size_t)b * SEQLEN * DINNER + d;

    float h = 0.f;
    // prefetch step 0
    float dt = dl[0];
    float u  = us[0];
    float Bn = xd[DTRANK + n];
    float Cn = xd[DTRANK + DSTATE + n];

    for (int l = 0; l < SEQLEN; l++) {
        const float dt_c = dt, u_c = u, B_c = Bn, C_c = Cn;
        const int ln = (l + 1 < SEQLEN) ? (l + 1) : l;   // clamp
        dt = dl[(size_t)ln * DINNER];
        u  = us[(size_t)ln * DINNER];
        Bn = xd[(size_t)ln * 64 + DTRANK + n];
        Cn = xd[(size_t)ln * 64 + DTRANK + DSTATE + n];

        const float dA = __expf(dt_c * A_dn);
        h = fmaf(dA, h, dt_c * u_c * B_c);
        float p = h * C_c;
        // reduce across the 16 state lanes
        p += __shfl_xor_sync(0xffffffffu, p, 8, 16);
        p += __shfl_xor_sync(0xffffffffu, p, 4, 16);
        p += __shfl_xor_sync(0xffffffffu, p, 2, 16);
        p += __shfl_xor_sync(0xffffffffu, p, 1, 16);
        if (n == 0) {
            const float z = zp[(size_t)l * (2 * DINNER)];
            const float sz = z / (1.f + __expf(-z));
            yp[(size_t)l * DINNER] = (p + u_c * Dd) * sz;
        }
    }
}

// ---------------------------------------------------------------------------
extern "C" void kernel_launch(void* const* d_in, const int* in_sizes, int n_in,
                              void* d_out, int out_size)
{
    const float* x          = (const float*)d_in[0];
    const float* in_proj_w  = (const float*)d_in[1];
    const float* conv_w     = (const float*)d_in[2];
    const float* conv_b     = (const float*)d_in[3];
    const float* x_proj_w   = (const float*)d_in[4];
    const float* dt_proj_w  = (const float*)d_in[5];
    const float* dt_proj_b  = (const float*)d_in[6];
    const float* A_log      = (const float*)d_in[7];
    const float* D_param    = (const float*)d_in[8];
    const float* out_proj_w = (const float*)d_in[9];
    float* out = (float*)d_out;

    // 1) in_proj: x[4096,512] x in_proj_w[2048,512]^T -> g_xz [4096,2048]
    gemm_nt<1><<<dim3(2 * DINNER / 64, MROWS / 64), 256>>>(x, in_proj_w, nullptr, nullptr);

    // 2) depthwise causal conv + SiLU -> g_xs [4096,1024]
    conv_silu_kernel<<<MROWS, 256>>>(conv_w, conv_b);

    // 3) x_proj: g_xs[4096,1024] x x_proj_w[64,1024]^T -> g_xdbl [4096,64]
    gemm_nt<3><<<dim3(1, MROWS / 64), 256>>>(nullptr, x_proj_w, nullptr, nullptr);

    // 4) dt_proj + softplus: g_xdbl[:, :32] x dt_proj_w[1024,32]^T -> g_delta
    gemm_nt<4><<<dim3(DINNER / 64, MROWS / 64), 256>>>(nullptr, dt_proj_w, nullptr, dt_proj_b);

    // 5) selective scan + skip + gate -> g_y [4096,1024]
    scan_kernel<<<BATCH * DINNER / 8, 128>>>(A_log, D_param);

    // 6) out_proj: g_y[4096,1024] x out_proj_w[512,1024]^T -> out [4096,512]
    gemm_nt<6><<<dim3(DMODEL / 64, MROWS / 64), 256>>>(nullptr, out_proj_w, out, nullptr);
}

// round 3
// speedup vs baseline: 1.2379x; 1.2379x over previous
#include <cuda_runtime.h>
#include <cuda_bf16.h>
#include <cstdint>

// ---------------------------------------------------------------------------
// Mamba block forward.  B=2, L=2048, d_model=512, d_inner=1024, d_state=16,
// dt_rank=32, d_conv=4.
// Stages:
//  1 in_proj   (tf32 mma)   x[4096,512]   @ W[2048,512]^T  -> g_xz[4096,2048]
//  2 conv+silu (elementwise)                              -> g_xs
//  3 x_proj    (fp32 SIMT)  g_xs          @ W[64,1024]^T   -> g_xdbl[4096,64]
//  4 dt_proj   (fp32 SIMT)  g_xdbl[:, :32]@ W[1024,32]^T   -> g_delta (softplus)
//  5 scan      (serial in L, parallel over 2048 channels)  -> g_y
//  6 out_proj  (tf32 mma)   g_y           @ W[512,1024]^T  -> out[4096,512]
// ---------------------------------------------------------------------------

#define BATCH    2
#define SEQLEN   2048
#define DMODEL   512
#define DINNER   1024
#define DSTATE   16
#define DTRANK   32
#define DCONV    4
#define MROWS    (BATCH * SEQLEN)        // 4096

// Scratch (device-global; no runtime allocation allowed)
__device__ float g_xz[(size_t)MROWS * 2 * DINNER];    // [4096, 2048]  xs | z
__device__ float g_xs[(size_t)MROWS * DINNER];        // conv+silu output
__device__ float g_xdbl[(size_t)MROWS * 64];          // [4096, 64]
__device__ float g_delta[(size_t)MROWS * DINNER];     // softplus(dt@W + b)
__device__ float g_y[(size_t)MROWS * DINNER];         // scan output (gated)

// ---------------------------------------------------------------------------
__device__ __forceinline__ uint32_t f2tf32(float f) {
    uint32_t r;
    asm("cvt.rna.tf32.f32 %0, %1;" : "=r"(r) : "f"(f));
    return r;
}

__device__ __forceinline__ void mma_tf32(float c[4], const uint32_t a[4],
                                         uint32_t b0, uint32_t b1) {
    asm volatile(
        "mma.sync.aligned.m16n8k8.row.col.f32.tf32.tf32.f32 "
        "{%0,%1,%2,%3}, {%4,%5,%6,%7}, {%8,%9}, {%0,%1,%2,%3};"
        : "+f"(c[0]), "+f"(c[1]), "+f"(c[2]), "+f"(c[3])
        : "r"(a[0]), "r"(a[1]), "r"(a[2]), "r"(a[3]), "r"(b0), "r"(b1));
}

// ---------------------------------------------------------------------------
// Tensor-core NT GEMM (tf32): C[m,n] = sum_k A[m,k] * W[n,k]
// BM=BN=128, BK=16.  256 threads = 8 warps (4 in m, 2 in n); warp tile 32x64
// = 2 m-atoms x 8 n-atoms of m16n8k8.
// Smem stride 20 (=BK+4): addr = 20*row + k; for the fragment gather
// (8 rows x 4 k per warp quad-group) 20*m mod 32 lands each m on a disjoint
// 4-bank quad -> conflict-free.
//   STAGE 1: A=param x,  C=g_xz, lda=512,  ldc=2048, K=512
//   STAGE 6: A=g_y,      C=param, lda=1024, ldc=512, K=1024
// ---------------------------------------------------------------------------
template <int STAGE>
__global__ void __launch_bounds__(256)
gemm_mma(const float* __restrict__ Ap,
         const float* __restrict__ W,
         float* __restrict__ Cp)
{
    constexpr int BM = 128, BN = 128, BK = 16, SST = BK + 4;  // smem stride

    const float* A;
    float* C;
    int lda, ldw, ldc, K;
    if constexpr (STAGE == 1) {
        A = Ap;  C = g_xz; lda = DMODEL; ldw = DMODEL; ldc = 2 * DINNER; K = DMODEL;
    } else {  // STAGE == 6
        A = g_y; C = Cp;   lda = DINNER; ldw = DINNER; ldc = DMODEL;     K = DINNER;
    }

    __shared__ uint32_t As[BM][SST];
    __shared__ uint32_t Bs[BN][SST];

    const int tid = threadIdx.x;
    const int lane = tid & 31;
    const int wid = tid >> 5;
    const int wm = (wid & 3) * 32;      // warp m offset within tile
    const int wn = (wid >> 2) * 64;     // warp n offset within tile
    const int g  = lane >> 2;           // 0..7
    const int tg = lane & 3;            // 0..3

    const int m0 = blockIdx.y * BM;
    const int n0 = blockIdx.x * BN;

    // gmem->reg staging: 2 float4 of A and 2 of B per thread per ktile
    const int lr0 = tid >> 2;                 // 0..63   (rows 0..63)
    const int lr1 = lr0 + 64;                 // rows 64..127
    const int lc4 = (tid & 3) * 4;            // k offset 0,4,8,12

    const float* Ar0 = A + (size_t)(m0 + lr0) * lda + lc4;
    const float* Ar1 = A + (size_t)(m0 + lr1) * lda + lc4;
    const float* Wr0 = W + (size_t)(n0 + lr0) * ldw + lc4;
    const float* Wr1 = W + (size_t)(n0 + lr1) * ldw + lc4;

    float c[2][8][4];
#pragma unroll
    for (int i = 0; i < 2; i++)
#pragma unroll
        for (int j = 0; j < 8; j++)
#pragma unroll
            for (int r = 0; r < 4; r++) c[i][j][r] = 0.f;

    float4 av0 = *(const float4*)(Ar0);
    float4 av1 = *(const float4*)(Ar1);
    float4 wv0 = *(const float4*)(Wr0);
    float4 wv1 = *(const float4*)(Wr1);

#pragma unroll 1
    for (int k0 = 0; k0 < K; k0 += BK) {
        __syncthreads();
        As[lr0][lc4 + 0] = f2tf32(av0.x); As[lr0][lc4 + 1] = f2tf32(av0.y);
        As[lr0][lc4 + 2] = f2tf32(av0.z); As[lr0][lc4 + 3] = f2tf32(av0.w);
        As[lr1][lc4 + 0] = f2tf32(av1.x); As[lr1][lc4 + 1] = f2tf32(av1.y);
        As[lr1][lc4 + 2] = f2tf32(av1.z); As[lr1][lc4 + 3] = f2tf32(av1.w);
        Bs[lr0][lc4 + 0] = f2tf32(wv0.x); Bs[lr0][lc4 + 1] = f2tf32(wv0.y);
        Bs[lr0][lc4 + 2] = f2tf32(wv0.z); Bs[lr0][lc4 + 3] = f2tf32(wv0.w);
        Bs[lr1][lc4 + 0] = f2tf32(wv1.x); Bs[lr1][lc4 + 1] = f2tf32(wv1.y);
        Bs[lr1][lc4 + 2] = f2tf32(wv1.z); Bs[lr1][lc4 + 3] = f2tf32(wv1.w);
        __syncthreads();

        if (k0 + BK < K) {   // prefetch next ktile while computing
            av0 = *(const float4*)(Ar0 + k0 + BK);
            av1 = *(const float4*)(Ar1 + k0 + BK);
            wv0 = *(const float4*)(Wr0 + k0 + BK);
            wv1 = *(const float4*)(Wr1 + k0 + BK);
        }

#pragma unroll
        for (int kk = 0; kk < 2; kk++) {
            const int kb = kk * 8;
            uint32_t a[2][4];
#pragma unroll
            for (int i = 0; i < 2; i++) {
                const int m = wm + i * 16 + g;
                a[i][0] = As[m][kb + tg];
                a[i][1] = As[m + 8][kb + tg];
                a[i][2] = As[m][kb + tg + 4];
                a[i][3] = As[m + 8][kb + tg + 4];
            }
#pragma unroll
            for (int j = 0; j < 8; j++) {
                const int n = wn + j * 8 + g;
                const uint32_t b0 = Bs[n][kb + tg];
                const uint32_t b1 = Bs[n][kb + tg + 4];
                mma_tf32(c[0][j], a[0], b0, b1);
                mma_tf32(c[1][j], a[1], b0, b1);
            }
        }
    }

    // epilogue: c[i][j] -> rows (wm+16i+g, +8), cols (wn+8j+2*tg, +1)
#pragma unroll
    for (int i = 0; i < 2; i++) {
        const int mrow0 = m0 + wm + i * 16 + g;
#pragma unroll
        for (int j = 0; j < 8; j++) {
            const int ncol = n0 + wn + j * 8 + 2 * tg;
            *(float2*)&C[(size_t)mrow0 * ldc + ncol] =
                make_float2(c[i][j][0], c[i][j][1]);
            *(float2*)&C[(size_t)(mrow0 + 8) * ldc + ncol] =
                make_float2(c[i][j][2], c[i][j][3]);
        }
    }
}

// ---------------------------------------------------------------------------
// Small fp32 SIMT GEMM for stages 3 & 4 (kept from R2).
// ---------------------------------------------------------------------------
template <int STAGE>
__global__ void __launch_bounds__(256)
gemm_nt(const float* __restrict__ W,
        const float* __restrict__ bias)
{
    constexpr int BM = 64, BN = 64, BK = 16;

    const float* A;
    float* C;
    int lda, ldw, ldc, K;
    if constexpr (STAGE == 3) {
        A = g_xs;   C = g_xdbl;  lda = DINNER; ldw = DINNER; ldc = 64;     K = DINNER;
    } else {  // STAGE == 4
        A = g_xdbl; C = g_delta; lda = 64;     ldw = DTRANK; ldc = DINNER; K = DTRANK;
    }

    __shared__ float As[BK][BM];
    __shared__ float Bs[BK][BN];

    const int tid = threadIdx.x;
    const int m0 = blockIdx.y * BM;
    const int n0 = blockIdx.x * BN;
    const int tx = tid & 15;
    const int ty = tid >> 4;
    const int lrow = tid >> 2;
    const int lc4 = (tid & 3) * 4;

    float acc[4][4];
#pragma unroll
    for (int i = 0; i < 4; i++)
#pragma unroll
        for (int j = 0; j < 4; j++) acc[i][j] = 0.f;

    const float* Arow = A + (size_t)(m0 + lrow) * lda + lc4;
    const float* Wrow = W + (size_t)(n0 + lrow) * ldw + lc4;

#pragma unroll 1
    for (int k0 = 0; k0 < K; k0 += BK) {
        float4 av = *(const float4*)(Arow + k0);
        float4 wv = *(const float4*)(Wrow + k0);
        __syncthreads();
        As[lc4 + 0][lrow] = av.x; As[lc4 + 1][lrow] = av.y;
        As[lc4 + 2][lrow] = av.z; As[lc4 + 3][lrow] = av.w;
        Bs[lc4 + 0][lrow] = wv.x; Bs[lc4 + 1][lrow] = wv.y;
        Bs[lc4 + 2][lrow] = wv.z; Bs[lc4 + 3][lrow] = wv.w;
        __syncthreads();
#pragma unroll
        for (int kk = 0; kk < BK; kk++) {
            float4 a4 = *(const float4*)&As[kk][ty * 4];
            float4 b4 = *(const float4*)&Bs[kk][tx * 4];
            float ar[4] = {a4.x, a4.y, a4.z, a4.w};
            float br[4] = {b4.x, b4.y, b4.z, b4.w};
#pragma unroll
            for (int i = 0; i < 4; i++)
#pragma unroll
                for (int j = 0; j < 4; j++)
                    acc[i][j] = fmaf(ar[i], br[j], acc[i][j]);
        }
    }

#pragma unroll
    for (int i = 0; i < 4; i++) {
        const int m = m0 + ty * 4 + i;
#pragma unroll
        for (int j = 0; j < 4; j++) {
            const int n = n0 + tx * 4 + j;
            float v = acc[i][j];
            if constexpr (STAGE == 4) {
                v += bias[n];
                v = (v > 20.f) ? v : log1pf(__expf(v));   // softplus
            }
            C[(size_t)m * ldc + n] = v;
        }
    }
}

// ---------------------------------------------------------------------------
// Causal depthwise conv1d (width 4) + SiLU on the xs half of g_xz.
// ---------------------------------------------------------------------------
__global__ void __launch_bounds__(256)
conv_silu_kernel(const float* __restrict__ conv_w,
                 const float* __restrict__ conv_b)
{
    const int bl = blockIdx.x;            // 0..4095  (= b*L + l)
    const int l = bl & (SEQLEN - 1);
    for (int d = threadIdx.x; d < DINNER; d += blockDim.x) {
        float acc = conv_b[d];
#pragma unroll
        for (int j = 0; j < DCONV; j++) {
            const int ls = l - (DCONV - 1) + j;
            if (ls >= 0)
                acc = fmaf(g_xz[(size_t)(bl - (DCONV - 1) + j) * (2 * DINNER) + d],
                           conv_w[d * DCONV + j], acc);
        }
        const float s = acc / (1.f + __expf(-acc));   // SiLU
        g_xs[(size_t)bl * DINNER + d] = s;
    }
}

// ---------------------------------------------------------------------------
// Selective scan.  One 16-lane group per (b,d) channel; lane n owns state n.
// ---------------------------------------------------------------------------
__global__ void __launch_bounds__(128)
scan_kernel(const float* __restrict__ A_log,
            const float* __restrict__ D_param)
{
    const int tid = threadIdx.x;
    const int half = tid >> 4;            // 0..7  channel within block
    const int n = tid & 15;               // state index
    const int hw = blockIdx.x * 8 + half; // global channel id
    const int b = hw >> 10;               // / 1024
    const int d = hw & (DINNER - 1);

    const float A_dn = -__expf(A_log[d * DSTATE + n]);
    const float Dd = D_param[d];

    const float* xd = g_xdbl + (size_t)b * SEQLEN * 64;
    const float* dl = g_delta + (size_t)b * SEQLEN * DINNER + d;
    const float* us = g_xs + (size_t)b * SEQLEN * DINNER + d;
    const float* zp = g_xz + (size_t)b * SEQLEN * (2 * DINNER) + DINNER + d;
    float* yp = g_y + (size_t)b * SEQLEN * DINNER + d;

    float h = 0.f;
    float dt = dl[0];
    float u  = us[0];
    float Bn = xd[DTRANK + n];
    float Cn = xd[DTRANK + DSTATE + n];

    for (int l = 0; l < SEQLEN; l++) {
        const float dt_c = dt, u_c = u, B_c = Bn, C_c = Cn;
        const int ln = (l + 1 < SEQLEN) ? (l + 1) : l;   // clamp
        dt = dl[(size_t)ln * DINNER];
        u  = us[(size_t)ln * DINNER];
        Bn = xd[(size_t)ln * 64 + DTRANK + n];
        Cn = xd[(size_t)ln * 64 + DTRANK + DSTATE + n];

        const float dA = __expf(dt_c * A_dn);
        h = fmaf(dA, h, dt_c * u_c * B_c);
        float p = h * C_c;
        p += __shfl_xor_sync(0xffffffffu, p, 8, 16);
        p += __shfl_xor_sync(0xffffffffu, p, 4, 16);
        p += __shfl_xor_sync(0xffffffffu, p, 2, 16);
        p += __shfl_xor_sync(0xffffffffu, p, 1, 16);
        if (n == 0) {
            const float z = zp[(size_t)l * (2 * DINNER)];
            const float sz = z / (1.f + __expf(-z));
            yp[(size_t)l * DINNER] = (p + u_c * Dd) * sz;
        }
    }
}

// ---------------------------------------------------------------------------
extern "C" void kernel_launch(void* const* d_in, const int* in_sizes, int n_in,
                              void* d_out, int out_size)
{
    const float* x          = (const float*)d_in[0];
    const float* in_proj_w  = (const float*)d_in[1];
    const float* conv_w     = (const float*)d_in[2];
    const float* conv_b     = (const float*)d_in[3];
    const float* x_proj_w   = (const float*)d_in[4];
    const float* dt_proj_w  = (const float*)d_in[5];
    const float* dt_proj_b  = (const float*)d_in[6];
    const float* A_log      = (const float*)d_in[7];
    const float* D_param    = (const float*)d_in[8];
    const float* out_proj_w = (const float*)d_in[9];
    float* out = (float*)d_out;

    // 1) in_proj (tf32 mma): -> g_xz [4096,2048]
    gemm_mma<1><<<dim3(2 * DINNER / 128, MROWS / 128), 256>>>(x, in_proj_w, nullptr);

    // 2) depthwise causal conv + SiLU -> g_xs [4096,1024]
    conv_silu_kernel<<<MROWS, 256>>>(conv_w, conv_b);

    // 3) x_proj: g_xs[4096,1024] x x_proj_w[64,1024]^T -> g_xdbl [4096,64]
    gemm_nt<3><<<dim3(1, MROWS / 64), 256>>>(x_proj_w, nullptr);

    // 4) dt_proj + softplus -> g_delta [4096,1024]
    gemm_nt<4><<<dim3(DINNER / 64, MROWS / 64), 256>>>(dt_proj_w, dt_proj_b);

    // 5) selective scan + skip + gate -> g_y [4096,1024]
    scan_kernel<<<BATCH * DINNER / 8, 128>>>(A_log, D_param);

    // 6) out_proj (tf32 mma): -> out [4096,512]
    gemm_mma<6><<<dim3(DMODEL / 128, MROWS / 128), 256>>>(nullptr, out_proj_w, out);
}

// round 4
// speedup vs baseline: 1.3163x; 1.0633x over previous
#include <cuda_runtime.h>
#include <cuda_bf16.h>
#include <cstdint>

// ---------------------------------------------------------------------------
// Mamba block forward.  B=2, L=2048, d_model=512, d_inner=1024, d_state=16,
// dt_rank=32, d_conv=4.
// ---------------------------------------------------------------------------

#define BATCH    2
#define SEQLEN   2048
#define DMODEL   512
#define DINNER   1024
#define DSTATE   16
#define DTRANK   32
#define DCONV    4
#define MROWS    (BATCH * SEQLEN)        // 4096

// Scratch (device-global; no runtime allocation allowed)
__device__ float g_xz[(size_t)MROWS * 2 * DINNER];    // [4096, 2048]  xs | z
__device__ float g_xs[(size_t)MROWS * DINNER];        // conv+silu output
__device__ float g_xdbl[(size_t)MROWS * 64];          // [4096, 64]
__device__ float g_delta[(size_t)MROWS * DINNER];     // softplus(dt@W + b)
__device__ float g_y[(size_t)MROWS * DINNER];         // scan output (gated)

// ---------------------------------------------------------------------------
__device__ __forceinline__ uint32_t f2tf32(float f) {
    uint32_t r;
    asm("cvt.rna.tf32.f32 %0, %1;" : "=r"(r) : "f"(f));
    return r;
}

__device__ __forceinline__ void mma_tf32(float c[4], const uint32_t a[4],
                                         uint32_t b0, uint32_t b1) {
    asm volatile(
        "mma.sync.aligned.m16n8k8.row.col.f32.tf32.tf32.f32 "
        "{%0,%1,%2,%3}, {%4,%5,%6,%7}, {%8,%9}, {%0,%1,%2,%3};"
        : "+f"(c[0]), "+f"(c[1]), "+f"(c[2]), "+f"(c[3])
        : "r"(a[0]), "r"(a[1]), "r"(a[2]), "r"(a[3]), "r"(b0), "r"(b1));
}

// ---------------------------------------------------------------------------
// Tensor-core NT GEMM (tf32): C[m,n] = sum_k A[m,k] * W[n,k]
// BM=BN=128, BK=16.  256 threads = 8 warps (4 in m, 2 in n); warp tile 32x64.
// Smem stride 20: fragment loads conflict-free; stores via uint4 STS.128.
//   STAGE 1: A=param x,  C=g_xz,  lda=512,  ldc=2048, K=512
//   STAGE 6: A=g_y,      C=param, lda=1024, ldc=512,  K=1024
// ---------------------------------------------------------------------------
template <int STAGE>
__global__ void __launch_bounds__(256)
gemm_mma(const float* __restrict__ Ap,
         const float* __restrict__ W,
         float* __restrict__ Cp)
{
    constexpr int BM = 128, BN = 128, BK = 16, SST = BK + 4;  // smem stride

    const float* A;
    float* C;
    int lda, ldw, ldc, K;
    if constexpr (STAGE == 1) {
        A = Ap;  C = g_xz; lda = DMODEL; ldw = DMODEL; ldc = 2 * DINNER; K = DMODEL;
    } else {  // STAGE == 6
        A = g_y; C = Cp;   lda = DINNER; ldw = DINNER; ldc = DMODEL;     K = DINNER;
    }

    __shared__ __align__(16) uint32_t As[BM][SST];
    __shared__ __align__(16) uint32_t Bs[BN][SST];

    const int tid = threadIdx.x;
    const int lane = tid & 31;
    const int wid = tid >> 5;
    const int wm = (wid & 3) * 32;      // warp m offset within tile
    const int wn = (wid >> 2) * 64;     // warp n offset within tile
    const int g  = lane >> 2;           // 0..7
    const int tg = lane & 3;            // 0..3

    const int m0 = blockIdx.y * BM;
    const int n0 = blockIdx.x * BN;

    const int lr0 = tid >> 2;                 // rows 0..63
    const int lr1 = lr0 + 64;                 // rows 64..127
    const int lc4 = (tid & 3) * 4;            // k offset 0,4,8,12

    const float* Ar0 = A + (size_t)(m0 + lr0) * lda + lc4;
    const float* Ar1 = A + (size_t)(m0 + lr1) * lda + lc4;
    const float* Wr0 = W + (size_t)(n0 + lr0) * ldw + lc4;
    const float* Wr1 = W + (size_t)(n0 + lr1) * ldw + lc4;

    float c[2][8][4];
#pragma unroll
    for (int i = 0; i < 2; i++)
#pragma unroll
        for (int j = 0; j < 8; j++)
#pragma unroll
            for (int r = 0; r < 4; r++) c[i][j][r] = 0.f;

    float4 av0 = *(const float4*)(Ar0);
    float4 av1 = *(const float4*)(Ar1);
    float4 wv0 = *(const float4*)(Wr0);
    float4 wv1 = *(const float4*)(Wr1);

#pragma unroll 1
    for (int k0 = 0; k0 < K; k0 += BK) {
        __syncthreads();
        {
            uint4 p;
            p.x = f2tf32(av0.x); p.y = f2tf32(av0.y);
            p.z = f2tf32(av0.z); p.w = f2tf32(av0.w);
            *(uint4*)&As[lr0][lc4] = p;
            p.x = f2tf32(av1.x); p.y = f2tf32(av1.y);
            p.z = f2tf32(av1.z); p.w = f2tf32(av1.w);
            *(uint4*)&As[lr1][lc4] = p;
            p.x = f2tf32(wv0.x); p.y = f2tf32(wv0.y);
            p.z = f2tf32(wv0.z); p.w = f2tf32(wv0.w);
            *(uint4*)&Bs[lr0][lc4] = p;
            p.x = f2tf32(wv1.x); p.y = f2tf32(wv1.y);
            p.z = f2tf32(wv1.z); p.w = f2tf32(wv1.w);
            *(uint4*)&Bs[lr1][lc4] = p;
        }
        __syncthreads();

        if (k0 + BK < K) {   // prefetch next ktile while computing
            av0 = *(const float4*)(Ar0 + k0 + BK);
            av1 = *(const float4*)(Ar1 + k0 + BK);
            wv0 = *(const float4*)(Wr0 + k0 + BK);
            wv1 = *(const float4*)(Wr1 + k0 + BK);
        }

#pragma unroll
        for (int kk = 0; kk < 2; kk++) {
            const int kb = kk * 8;
            uint32_t a[2][4];
#pragma unroll
            for (int i = 0; i < 2; i++) {
                const int m = wm + i * 16 + g;
                a[i][0] = As[m][kb + tg];
                a[i][1] = As[m + 8][kb + tg];
                a[i][2] = As[m][kb + tg + 4];
                a[i][3] = As[m + 8][kb + tg + 4];
            }
#pragma unroll
            for (int j = 0; j < 8; j++) {
                const int n = wn + j * 8 + g;
                const uint32_t b0 = Bs[n][kb + tg];
                const uint32_t b1 = Bs[n][kb + tg + 4];
                mma_tf32(c[0][j], a[0], b0, b1);
                mma_tf32(c[1][j], a[1], b0, b1);
            }
        }
    }

    // epilogue
#pragma unroll
    for (int i = 0; i < 2; i++) {
        const int mrow0 = m0 + wm + i * 16 + g;
#pragma unroll
        for (int j = 0; j < 8; j++) {
            const int ncol = n0 + wn + j * 8 + 2 * tg;
            *(float2*)&C[(size_t)mrow0 * ldc + ncol] =
                make_float2(c[i][j][0], c[i][j][1]);
            *(float2*)&C[(size_t)(mrow0 + 8) * ldc + ncol] =
                make_float2(c[i][j][2], c[i][j][3]);
        }
    }
}

// ---------------------------------------------------------------------------
// Small fp32 SIMT GEMM for stages 3 & 4.
// ---------------------------------------------------------------------------
template <int STAGE>
__global__ void __launch_bounds__(256)
gemm_nt(const float* __restrict__ W,
        const float* __restrict__ bias)
{
    constexpr int BM = 64, BN = 64, BK = 16;

    const float* A;
    float* C;
    int lda, ldw, ldc, K;
    if constexpr (STAGE == 3) {
        A = g_xs;   C = g_xdbl;  lda = DINNER; ldw = DINNER; ldc = 64;     K = DINNER;
    } else {  // STAGE == 4
        A = g_xdbl; C = g_delta; lda = 64;     ldw = DTRANK; ldc = DINNER; K = DTRANK;
    }

    __shared__ float As[BK][BM];
    __shared__ float Bs[BK][BN];

    const int tid = threadIdx.x;
    const int m0 = blockIdx.y * BM;
    const int n0 = blockIdx.x * BN;
    const int tx = tid & 15;
    const int ty = tid >> 4;
    const int lrow = tid >> 2;
    const int lc4 = (tid & 3) * 4;

    float acc[4][4];
#pragma unroll
    for (int i = 0; i < 4; i++)
#pragma unroll
        for (int j = 0; j < 4; j++) acc[i][j] = 0.f;

    const float* Arow = A + (size_t)(m0 + lrow) * lda + lc4;
    const float* Wrow = W + (size_t)(n0 + lrow) * ldw + lc4;

#pragma unroll 1
    for (int k0 = 0; k0 < K; k0 += BK) {
        float4 av = *(const float4*)(Arow + k0);
        float4 wv = *(const float4*)(Wrow + k0);
        __syncthreads();
        As[lc4 + 0][lrow] = av.x; As[lc4 + 1][lrow] = av.y;
        As[lc4 + 2][lrow] = av.z; As[lc4 + 3][lrow] = av.w;
        Bs[lc4 + 0][lrow] = wv.x; Bs[lc4 + 1][lrow] = wv.y;
        Bs[lc4 + 2][lrow] = wv.z; Bs[lc4 + 3][lrow] = wv.w;
        __syncthreads();
#pragma unroll
        for (int kk = 0; kk < BK; kk++) {
            float4 a4 = *(const float4*)&As[kk][ty * 4];
            float4 b4 = *(const float4*)&Bs[kk][tx * 4];
            float ar[4] = {a4.x, a4.y, a4.z, a4.w};
            float br[4] = {b4.x, b4.y, b4.z, b4.w};
#pragma unroll
            for (int i = 0; i < 4; i++)
#pragma unroll
                for (int j = 0; j < 4; j++)
                    acc[i][j] = fmaf(ar[i], br[j], acc[i][j]);
        }
    }

#pragma unroll
    for (int i = 0; i < 4; i++) {
        const int m = m0 + ty * 4 + i;
#pragma unroll
        for (int j = 0; j < 4; j++) {
            const int n = n0 + tx * 4 + j;
            float v = acc[i][j];
            if constexpr (STAGE == 4) {
                v += bias[n];
                v = (v > 20.f) ? v : log1pf(__expf(v));   // softplus
            }
            C[(size_t)m * ldc + n] = v;
        }
    }
}

// ---------------------------------------------------------------------------
// Causal depthwise conv1d (width 4) + SiLU on the xs half of g_xz.
// ---------------------------------------------------------------------------
__global__ void __launch_bounds__(256)
conv_silu_kernel(const float* __restrict__ conv_w,
                 const float* __restrict__ conv_b)
{
    const int bl = blockIdx.x;            // 0..4095  (= b*L + l)
    const int l = bl & (SEQLEN - 1);
    for (int d = threadIdx.x; d < DINNER; d += blockDim.x) {
        float acc = conv_b[d];
#pragma unroll
        for (int j = 0; j < DCONV; j++) {
            const int ls = l - (DCONV - 1) + j;
            if (ls >= 0)
                acc = fmaf(g_xz[(size_t)(bl - (DCONV - 1) + j) * (2 * DINNER) + d],
                           conv_w[d * DCONV + j], acc);
        }
        const float s = acc / (1.f + __expf(-acc));   // SiLU
        g_xs[(size_t)bl * DINNER + d] = s;
    }
}

// ---------------------------------------------------------------------------
// Selective scan with chunked, double-buffered register prefetch.
// One 16-lane group per (b,d) channel; lane n owns state n.
// CH=8 steps per chunk: next chunk's loads are issued (MLP ~40) before the
// current chunk's compute, so L2 latency is exposed once per 8 steps.
// ---------------------------------------------------------------------------
#define SCH 8
__global__ void __launch_bounds__(128)
scan_kernel(const float* __restrict__ A_log,
            const float* __restrict__ D_param)
{
    const int tid = threadIdx.x;
    const int half = tid >> 4;            // 0..7  channel within block
    const int n = tid & 15;               // state index
    const int hw = blockIdx.x * 8 + half; // global channel id
    const int b = hw >> 10;               // / 1024
    const int d = hw & (DINNER - 1);

    const float A_dn = -__expf(A_log[d * DSTATE + n]);
    const float Dd = D_param[d];

    const float* xd = g_xdbl + (size_t)b * SEQLEN * 64;
    const float* dl = g_delta + (size_t)b * SEQLEN * DINNER + d;
    const float* us = g_xs + (size_t)b * SEQLEN * DINNER + d;
    const float* zp = g_xz + (size_t)b * SEQLEN * (2 * DINNER) + DINNER + d;
    float* yp = g_y + (size_t)b * SEQLEN * DINNER + d;

    float bdt[2][SCH], bu[2][SCH], bB[2][SCH], bC[2][SCH], bz[2][SCH];

    // load chunk 0 into buffer 0
#pragma unroll
    for (int j = 0; j < SCH; j++) {
        bdt[0][j] = dl[(size_t)j * DINNER];
        bu[0][j]  = us[(size_t)j * DINNER];
        bB[0][j]  = xd[j * 64 + DTRANK + n];
        bC[0][j]  = xd[j * 64 + DTRANK + DSTATE + n];
        bz[0][j]  = zp[(size_t)j * (2 * DINNER)];
    }

    float h = 0.f;
    int pb = 0;
#pragma unroll 1
    for (int l0 = 0; l0 < SEQLEN; l0 += SCH) {
        const int nb = pb ^ 1;
        if (l0 + SCH < SEQLEN) {
            const int base = l0 + SCH;
#pragma unroll
            for (int j = 0; j < SCH; j++) {
                bdt[nb][j] = dl[(size_t)(base + j) * DINNER];
                bu[nb][j]  = us[(size_t)(base + j) * DINNER];
                bB[nb][j]  = xd[(base + j) * 64 + DTRANK + n];
                bC[nb][j]  = xd[(base + j) * 64 + DTRANK + DSTATE + n];
                bz[nb][j]  = zp[(size_t)(base + j) * (2 * DINNER)];
            }
        }
#pragma unroll
        for (int j = 0; j < SCH; j++) {
            const float dt_c = bdt[pb][j];
            const float dA = __expf(dt_c * A_dn);
            h = fmaf(dA, h, dt_c * bu[pb][j] * bB[pb][j]);
            float p = h * bC[pb][j];
            p += __shfl_xor_sync(0xffffffffu, p, 8, 16);
            p += __shfl_xor_sync(0xffffffffu, p, 4, 16);
            p += __shfl_xor_sync(0xffffffffu, p, 2, 16);
            p += __shfl_xor_sync(0xffffffffu, p, 1, 16);
            if (n == 0) {
                const float z = bz[pb][j];
                const float sz = z / (1.f + __expf(-z));
                yp[(size_t)(l0 + j) * DINNER] = (p + bu[pb][j] * Dd) * sz;
            }
        }
        pb = nb;
    }
}

// ---------------------------------------------------------------------------
extern "C" void kernel_launch(void* const* d_in, const int* in_sizes, int n_in,
                              void* d_out, int out_size)
{
    const float* x          = (const float*)d_in[0];
    const float* in_proj_w  = (const float*)d_in[1];
    const float* conv_w     = (const float*)d_in[2];
    const float* conv_b     = (const float*)d_in[3];
    const float* x_proj_w   = (const float*)d_in[4];
    const float* dt_proj_w  = (const float*)d_in[5];
    const float* dt_proj_b  = (const float*)d_in[6];
    const float* A_log      = (const float*)d_in[7];
    const float* D_param    = (const float*)d_in[8];
    const float* out_proj_w = (const float*)d_in[9];
    float* out = (float*)d_out;

    // 1) in_proj (tf32 mma): -> g_xz [4096,2048]
    gemm_mma<1><<<dim3(2 * DINNER / 128, MROWS / 128), 256>>>(x, in_proj_w, nullptr);

    // 2) depthwise causal conv + SiLU -> g_xs [4096,1024]
    conv_silu_kernel<<<MROWS, 256>>>(conv_w, conv_b);

    // 3) x_proj: g_xs[4096,1024] x x_proj_w[64,1024]^T -> g_xdbl [4096,64]
    gemm_nt<3><<<dim3(1, MROWS / 64), 256>>>(x_proj_w, nullptr);

    // 4) dt_proj + softplus -> g_delta [4096,1024]
    gemm_nt<4><<<dim3(DINNER / 64, MROWS / 64), 256>>>(dt_proj_w, dt_proj_b);

    // 5) selective scan + skip + gate -> g_y [4096,1024]
    scan_kernel<<<BATCH * DINNER / 8, 128>>>(A_log, D_param);

    // 6) out_proj (tf32 mma): -> out [4096,512]
    gemm_mma<6><<<dim3(DMODEL / 128, MROWS / 128), 256>>>(nullptr, out_proj_w, out);
}